// round 1
// baseline (speedup 1.0000x reference)
#include <cuda_runtime.h>

// EMA scan: out[b,t,d] = alpha*out[b,t-1,d] + (1-alpha)*x[b,t,d], out[b,-1,d]=0
// Shapes fixed by the problem: B=4, S=4096, D=2048, fp32.

#define B 4
#define S 4096
#define D 2048
#define NCHUNK 32
#define CHUNK (S / NCHUNK)   // 128

__device__ __constant__ float kAlpha = 0.99f;
__device__ __constant__ float kOneM  = 0.01f;

// alpha^CHUNK computed at compile time in double, stored as float
constexpr float pow_alpha(int n) {
    double r = 1.0;
    for (int i = 0; i < n; ++i) r *= 0.99;
    return (float)r;
}
__device__ __constant__ float kDecay = pow_alpha(CHUNK);

// Scratch (allocation-free): chunk-end local EMAs and per-chunk carries.
// Layout: [b][chunk][d]
__device__ float g_ends [B * NCHUNK * D];
__device__ float g_carry[B * NCHUNK * D];

// ---------------------------------------------------------------------------
// Pass 1: per-(b,chunk,d) local EMA from 0; store only the chunk-end value.
// grid: (D/256, NCHUNK, B), block: 256
// ---------------------------------------------------------------------------
__global__ void __launch_bounds__(256) ema_pass1(const float* __restrict__ x) {
    const int d = blockIdx.x * blockDim.x + threadIdx.x;
    const int c = blockIdx.y;
    const int b = blockIdx.z;

    const float* xp = x + ((size_t)b * S + (size_t)c * CHUNK) * D + d;

    float ema = 0.0f;
    const float a = kAlpha, om = kOneM;

#pragma unroll 4
    for (int t0 = 0; t0 < CHUNK; t0 += 8) {
        float v[8];
#pragma unroll
        for (int j = 0; j < 8; ++j) v[j] = xp[(size_t)(t0 + j) * D];
#pragma unroll
        for (int j = 0; j < 8; ++j) ema = a * ema + om * v[j];
    }

    g_ends[((size_t)b * NCHUNK + c) * D + d] = ema;
}

// ---------------------------------------------------------------------------
// Pass 2: per-channel exclusive prefix over chunk ends with decay alpha^CHUNK.
// carry[b][c][d] = global EMA at the end of chunk c-1 (0 for c==0).
// grid: (B*D/256), block: 256  -> 8192 threads, 32 serial steps each.
// ---------------------------------------------------------------------------
__global__ void __launch_bounds__(256) ema_pass2() {
    const int ch = blockIdx.x * blockDim.x + threadIdx.x;  // 0..B*D-1
    const int b = ch / D;
    const int d = ch % D;

    // Prefetch all chunk ends (independent of the serial E chain).
    float e[NCHUNK];
#pragma unroll
    for (int c = 0; c < NCHUNK; ++c)
        e[c] = g_ends[((size_t)b * NCHUNK + c) * D + d];

    float E = 0.0f;
    const float dec = kDecay;
#pragma unroll
    for (int c = 0; c < NCHUNK; ++c) {
        g_carry[((size_t)b * NCHUNK + c) * D + d] = E;
        E = dec * E + e[c];
    }
}

// ---------------------------------------------------------------------------
// Pass 3: re-scan each chunk seeded with its carry (exact global recurrence),
// write all outputs.
// grid: (D/256, NCHUNK, B), block: 256
// ---------------------------------------------------------------------------
__global__ void __launch_bounds__(256) ema_pass3(const float* __restrict__ x,
                                                 float* __restrict__ out) {
    const int d = blockIdx.x * blockDim.x + threadIdx.x;
    const int c = blockIdx.y;
    const int b = blockIdx.z;

    const size_t base = ((size_t)b * S + (size_t)c * CHUNK) * D + d;
    const float* xp = x + base;
    float* op = out + base;

    float ema = g_carry[((size_t)b * NCHUNK + c) * D + d];
    const float a = kAlpha, om = kOneM;

#pragma unroll 4
    for (int t0 = 0; t0 < CHUNK; t0 += 8) {
        float v[8];
#pragma unroll
        for (int j = 0; j < 8; ++j) v[j] = xp[(size_t)(t0 + j) * D];
        float r[8];
#pragma unroll
        for (int j = 0; j < 8; ++j) {
            ema = a * ema + om * v[j];
            r[j] = ema;
        }
#pragma unroll
        for (int j = 0; j < 8; ++j) op[(size_t)(t0 + j) * D] = r[j];
    }
}

extern "C" void kernel_launch(void* const* d_in, const int* in_sizes, int n_in,
                              void* d_out, int out_size) {
    const float* x = (const float*)d_in[0];
    float* out = (float*)d_out;

    dim3 grid1(D / 256, NCHUNK, B);
    ema_pass1<<<grid1, 256>>>(x);
    ema_pass2<<<(B * D) / 256, 256>>>();
    ema_pass3<<<grid1, 256>>>(x, out);
}